// round 4
// baseline (speedup 1.0000x reference)
#include <cuda_runtime.h>

constexpr int B = 16, C = 64, H = 256, W = 256;
constexpr int PLANES = B * C;        // 1024
constexpr int PLANE_ELEMS = H * W;   // 65536
constexpr int RPT = 2;               // output rows per thread

struct RowT { float4 a, b; float l, r; };   // cols w0-1 .. w0+8 (10 vals)

__device__ __forceinline__ RowT load_row(const float* __restrict__ plane,
                                         int rr, int w0, int lane)
{
    RowT t;
    if (rr < 0 || rr >= H) {
        t.a = make_float4(0.f, 0.f, 0.f, 0.f);
        t.b = t.a; t.l = 0.f; t.r = 0.f;
        return t;
    }
    const float* rp = plane + rr * W + w0;
    t.a = *reinterpret_cast<const float4*>(rp);
    t.b = *reinterpret_cast<const float4*>(rp + 4);
    // Warp spans the full 256-col row: halos at lanes 0/31 are the zero pad.
    float lv = __shfl_up_sync(0xffffffffu, t.b.w, 1);
    float rv = __shfl_down_sync(0xffffffffu, t.a.x, 1);
    t.l = (lane == 0)  ? 0.f : lv;
    t.r = (lane == 31) ? 0.f : rv;
    return t;
}

__device__ __forceinline__ void acc_row(float o[8], const RowT& t,
                                        float k0, float k1, float k2)
{
    const float v0 = t.l,   v1 = t.a.x, v2 = t.a.y, v3 = t.a.z, v4 = t.a.w;
    const float v5 = t.b.x, v6 = t.b.y, v7 = t.b.z, v8 = t.b.w, v9 = t.r;
    o[0] += k0*v0 + k1*v1 + k2*v2;
    o[1] += k0*v1 + k1*v2 + k2*v3;
    o[2] += k0*v2 + k1*v3 + k2*v4;
    o[3] += k0*v3 + k1*v4 + k2*v5;
    o[4] += k0*v4 + k1*v5 + k2*v6;
    o[5] += k0*v5 + k1*v6 + k2*v7;
    o[6] += k0*v6 + k1*v7 + k2*v8;
    o[7] += k0*v7 + k1*v8 + k2*v9;
}

// Block (32, 8): one warp per y-slice, warp covers full 256-col row.
// Each thread: 8 cols x RPT rows. Block covers 8*RPT = 16 rows.
// Grid: (1, H/16 = 16, PLANES = 1024)
__global__ __launch_bounds__(256, 5) void ParConv2d_kernel(
    const float* __restrict__ x,
    const float* __restrict__ kern,
    float* __restrict__ y)
{
    const int p    = blockIdx.z;
    const int b    = p >> 6;
    const int lane = threadIdx.x;            // 0..31
    const int w0   = lane << 3;              // 8 cols per thread
    const int row0 = blockIdx.y * (8 * RPT) + threadIdx.y * RPT;

    const float* kb = kern + b * 9;
    const float k00 = kb[0], k01 = kb[1], k02 = kb[2];
    const float k10 = kb[3], k11 = kb[4], k12 = kb[5];
    const float k20 = kb[6], k21 = kb[7], k22 = kb[8];

    const float* plane  = x + (size_t)p * PLANE_ELEMS;
    float*       oplane = y + (size_t)p * PLANE_ELEMS;

    RowT r0 = load_row(plane, row0 - 1, w0, lane);
    RowT r1 = load_row(plane, row0,     w0, lane);

    #pragma unroll
    for (int i = 0; i < RPT; ++i) {
        RowT r2 = load_row(plane, row0 + 1 + i, w0, lane);

        float o[8] = {0.f, 0.f, 0.f, 0.f, 0.f, 0.f, 0.f, 0.f};
        acc_row(o, r0, k00, k01, k02);
        acc_row(o, r1, k10, k11, k12);
        acc_row(o, r2, k20, k21, k22);

        float* op = oplane + (row0 + i) * W + w0;
        __stcs(reinterpret_cast<float4*>(op),     make_float4(o[0], o[1], o[2], o[3]));
        __stcs(reinterpret_cast<float4*>(op + 4), make_float4(o[4], o[5], o[6], o[7]));

        r0 = r1; r1 = r2;
    }
}

extern "C" void kernel_launch(void* const* d_in, const int* in_sizes, int n_in,
                              void* d_out, int out_size)
{
    const float* x    = (const float*)d_in[0];   // (B, C, H, W) fp32
    const float* kern = (const float*)d_in[1];   // (B, 3, 3) fp32
    float*       y    = (float*)d_out;

    dim3 block(32, 8, 1);                    // 256 threads
    dim3 grid(1, H / (8 * RPT), PLANES);     // (1, 16, 1024)
    ParConv2d_kernel<<<grid, block>>>(x, kern, y);
}

// round 5
// speedup vs baseline: 1.0580x; 1.0580x over previous
#include <cuda_runtime.h>

constexpr int B = 16, C = 64, H = 256, W = 256;
constexpr int PLANES = B * C;        // 1024
constexpr int PLANE_ELEMS = H * W;   // 65536
constexpr int RPT = 8;               // output rows per thread

struct RowT { float4 a, b; float l, r; };   // cols w0-1 .. w0+8 (10 vals)

__device__ __forceinline__ RowT load_row(const float* __restrict__ plane,
                                         int rr, int w0, int lane)
{
    RowT t;
    if (rr < 0 || rr >= H) {
        t.a = make_float4(0.f, 0.f, 0.f, 0.f);
        t.b = t.a; t.l = 0.f; t.r = 0.f;
        return t;
    }
    const float* rp = plane + rr * W + w0;
    t.a = *reinterpret_cast<const float4*>(rp);
    t.b = *reinterpret_cast<const float4*>(rp + 4);
    // Warp spans the full 256-col row: halos at lanes 0/31 are the zero pad.
    float lv = __shfl_up_sync(0xffffffffu, t.b.w, 1);
    float rv = __shfl_down_sync(0xffffffffu, t.a.x, 1);
    t.l = (lane == 0)  ? 0.f : lv;
    t.r = (lane == 31) ? 0.f : rv;
    return t;
}

__device__ __forceinline__ void acc_row(float o[8], const RowT& t,
                                        float k0, float k1, float k2)
{
    const float v0 = t.l,   v1 = t.a.x, v2 = t.a.y, v3 = t.a.z, v4 = t.a.w;
    const float v5 = t.b.x, v6 = t.b.y, v7 = t.b.z, v8 = t.b.w, v9 = t.r;
    o[0] += k0*v0 + k1*v1 + k2*v2;
    o[1] += k0*v1 + k1*v2 + k2*v3;
    o[2] += k0*v2 + k1*v3 + k2*v4;
    o[3] += k0*v3 + k1*v4 + k2*v5;
    o[4] += k0*v4 + k1*v5 + k2*v6;
    o[5] += k0*v5 + k1*v6 + k2*v7;
    o[6] += k0*v6 + k1*v7 + k2*v8;
    o[7] += k0*v7 + k1*v8 + k2*v9;
}

// Block (32, 8): one warp per y-slice, warp covers full 256-col row.
// Each thread: 8 cols x RPT=8 rows (sliding 3-row register window).
// Block covers 8*RPT = 64 rows. Grid: (1, H/64 = 4, PLANES = 1024)
__global__ __launch_bounds__(256, 4) void ParConv2d_kernel(
    const float* __restrict__ x,
    const float* __restrict__ kern,
    float* __restrict__ y)
{
    const int p    = blockIdx.z;
    const int b    = p >> 6;
    const int lane = threadIdx.x;            // 0..31
    const int w0   = lane << 3;              // 8 cols per thread
    const int row0 = blockIdx.y * (8 * RPT) + threadIdx.y * RPT;

    const float* kb = kern + b * 9;
    const float k00 = kb[0], k01 = kb[1], k02 = kb[2];
    const float k10 = kb[3], k11 = kb[4], k12 = kb[5];
    const float k20 = kb[6], k21 = kb[7], k22 = kb[8];

    const float* plane  = x + (size_t)p * PLANE_ELEMS;
    float*       oplane = y + (size_t)p * PLANE_ELEMS;

    RowT r0 = load_row(plane, row0 - 1, w0, lane);
    RowT r1 = load_row(plane, row0,     w0, lane);

    #pragma unroll
    for (int i = 0; i < RPT; ++i) {
        RowT r2 = load_row(plane, row0 + 1 + i, w0, lane);

        float o[8] = {0.f, 0.f, 0.f, 0.f, 0.f, 0.f, 0.f, 0.f};
        acc_row(o, r0, k00, k01, k02);
        acc_row(o, r1, k10, k11, k12);
        acc_row(o, r2, k20, k21, k22);

        float* op = oplane + (row0 + i) * W + w0;
        *reinterpret_cast<float4*>(op)     = make_float4(o[0], o[1], o[2], o[3]);
        *reinterpret_cast<float4*>(op + 4) = make_float4(o[4], o[5], o[6], o[7]);

        r0 = r1; r1 = r2;
    }
}

extern "C" void kernel_launch(void* const* d_in, const int* in_sizes, int n_in,
                              void* d_out, int out_size)
{
    const float* x    = (const float*)d_in[0];   // (B, C, H, W) fp32
    const float* kern = (const float*)d_in[1];   // (B, 3, 3) fp32
    float*       y    = (float*)d_out;

    dim3 block(32, 8, 1);                    // 256 threads
    dim3 grid(1, H / (8 * RPT), PLANES);     // (1, 4, 1024)
    ParConv2d_kernel<<<grid, block>>>(x, kern, y);
}

// round 6
// speedup vs baseline: 1.1184x; 1.0571x over previous
#include <cuda_runtime.h>

constexpr int B = 16, C = 64, H = 256, W = 256;
constexpr int PLANES = B * C;        // 1024
constexpr int PLANE_ELEMS = H * W;   // 65536
constexpr int RPT = 8;               // output rows per thread

// Raw row data: two float4 loads (cols w0..w0+7). Halos resolved at use time.
struct RawRow { float4 a, b; };

__device__ __forceinline__ RawRow load_raw(const float* __restrict__ plane,
                                           int rr, int w0)
{
    RawRow t;
    if (rr < 0 || rr >= H) {
        t.a = make_float4(0.f, 0.f, 0.f, 0.f);
        t.b = t.a;
    } else {
        const float* rp = plane + rr * W + w0;
        t.a = *reinterpret_cast<const float4*>(rp);
        t.b = *reinterpret_cast<const float4*>(rp + 4);
    }
    return t;
}

// Accumulate one kernel-row over 8 outputs; halos via shfl at use time.
__device__ __forceinline__ void acc_row(float o[8], const RawRow& t, int lane,
                                        float k0, float k1, float k2)
{
    float lv = __shfl_up_sync(0xffffffffu, t.b.w, 1);
    float rv = __shfl_down_sync(0xffffffffu, t.a.x, 1);
    const float v0 = (lane == 0)  ? 0.f : lv;
    const float v9 = (lane == 31) ? 0.f : rv;
    const float v1 = t.a.x, v2 = t.a.y, v3 = t.a.z, v4 = t.a.w;
    const float v5 = t.b.x, v6 = t.b.y, v7 = t.b.z, v8 = t.b.w;
    o[0] += k0*v0 + k1*v1 + k2*v2;
    o[1] += k0*v1 + k1*v2 + k2*v3;
    o[2] += k0*v2 + k1*v3 + k2*v4;
    o[3] += k0*v3 + k1*v4 + k2*v5;
    o[4] += k0*v4 + k1*v5 + k2*v6;
    o[5] += k0*v5 + k1*v6 + k2*v7;
    o[6] += k0*v6 + k1*v7 + k2*v8;
    o[7] += k0*v7 + k1*v8 + k2*v9;
}

// Block (32, 8): one warp per y-slice, warp spans the full 256-col row.
// Each thread: 8 cols x RPT=8 rows, sliding 3-row window + 1-deep prefetch.
// Grid: (1, H/64 = 4, PLANES = 1024)
__global__ __launch_bounds__(256, 3) void ParConv2d_kernel(
    const float* __restrict__ x,
    const float* __restrict__ kern,
    float* __restrict__ y)
{
    const int p    = blockIdx.z;
    const int b    = p >> 6;
    const int lane = threadIdx.x;            // 0..31
    const int w0   = lane << 3;              // 8 cols per thread
    const int row0 = blockIdx.y * (8 * RPT) + threadIdx.y * RPT;

    const float* kb = kern + b * 9;
    const float k00 = kb[0], k01 = kb[1], k02 = kb[2];
    const float k10 = kb[3], k11 = kb[4], k12 = kb[5];
    const float k20 = kb[6], k21 = kb[7], k22 = kb[8];

    const float* plane  = x + (size_t)p * PLANE_ELEMS;
    float*       oplane = y + (size_t)p * PLANE_ELEMS;

    RawRow r0  = load_raw(plane, row0 - 1, w0);
    RawRow r1  = load_raw(plane, row0,     w0);
    RawRow nxt = load_raw(plane, row0 + 1, w0);

    #pragma unroll
    for (int i = 0; i < RPT; ++i) {
        RawRow r2 = nxt;
        if (i + 1 < RPT)                        // prefetch row for iteration i+1
            nxt = load_raw(plane, row0 + 2 + i, w0);

        float o[8] = {0.f, 0.f, 0.f, 0.f, 0.f, 0.f, 0.f, 0.f};
        acc_row(o, r0, lane, k00, k01, k02);   // independent of r2 / nxt
        acc_row(o, r1, lane, k10, k11, k12);
        acc_row(o, r2, lane, k20, k21, k22);

        float* op = oplane + (row0 + i) * W + w0;
        *reinterpret_cast<float4*>(op)     = make_float4(o[0], o[1], o[2], o[3]);
        *reinterpret_cast<float4*>(op + 4) = make_float4(o[4], o[5], o[6], o[7]);

        r0 = r1; r1 = r2;
    }
}

extern "C" void kernel_launch(void* const* d_in, const int* in_sizes, int n_in,
                              void* d_out, int out_size)
{
    const float* x    = (const float*)d_in[0];   // (B, C, H, W) fp32
    const float* kern = (const float*)d_in[1];   // (B, 3, 3) fp32
    float*       y    = (float*)d_out;

    dim3 block(32, 8, 1);                    // 256 threads
    dim3 grid(1, H / (8 * RPT), PLANES);     // (1, 4, 1024)
    ParConv2d_kernel<<<grid, block>>>(x, kern, y);
}